// round 3
// baseline (speedup 1.0000x reference)
#include <cuda_runtime.h>
#include <cuda_bf16.h>
#include <cstdint>

#define SEQ   512
#define BATCH 64
#define DIM   1024
#define HID   1024
#define NJ    4096            // 4 gates * HID
#define MROWS (SEQ*BATCH)     // 32768

// ---------------- scratch (static device allocs only) ----------------
__device__ float g_G[(size_t)SEQ * BATCH * NJ];          // [m][j] fp32
__device__ __nv_bfloat16 g_Xs[(size_t)MROWS * 2048];     // [m][hi(1024)|lo(1024)]
__device__ __nv_bfloat16 g_Ws[(size_t)NJ * 2048];        // [j][hi|lo]  (Wx^T)
__device__ float g_Wh[(size_t)HID * NJ];                 // [k][j] gate-concat fp32
__device__ float g_bias[NJ];                             // bx+bh
__device__ unsigned int g_bar_count;
__device__ unsigned int g_bar_gen;

struct GatePtrs {
    const float* Wx[4];
    const float* Wh[4];
    const float* bx[4];
    const float* bh[4];
};

// ---------------- small helpers ----------------
__device__ __forceinline__ uint32_t smem_to_u32(const void* p) {
    uint32_t a;
    asm("{ .reg .u64 t; cvta.to.shared.u64 t, %1; cvt.u32.u64 %0, t; }"
        : "=r"(a) : "l"(p));
    return a;
}
__device__ __forceinline__ void cp_async16(uint32_t saddr, const void* g) {
    asm volatile("cp.async.cg.shared.global [%0], [%1], 16;"
                 :: "r"(saddr), "l"(g) : "memory");
}
__device__ __forceinline__ void cp_commit() {
    asm volatile("cp.async.commit_group;" ::: "memory");
}
#define CP_WAIT2() asm volatile("cp.async.wait_group 2;" ::: "memory")

#define LDSM_X4(r0, r1, r2, r3, addr) \
    asm volatile("ldmatrix.sync.aligned.m8n8.x4.shared.b16 {%0,%1,%2,%3}, [%4];" \
        : "=r"(r0), "=r"(r1), "=r"(r2), "=r"(r3) : "r"(addr))

__device__ __forceinline__ void mma_bf16(float* c, const uint32_t* a, const uint32_t* b) {
    asm volatile(
        "mma.sync.aligned.m16n8k16.row.col.f32.bf16.bf16.f32 "
        "{%0,%1,%2,%3}, {%4,%5,%6,%7}, {%8,%9}, {%0,%1,%2,%3};"
        : "+f"(c[0]), "+f"(c[1]), "+f"(c[2]), "+f"(c[3])
        : "r"(a[0]), "r"(a[1]), "r"(a[2]), "r"(a[3]), "r"(b[0]), "r"(b[1]));
}

// f32x2 (packed fp32) helpers for the recurrence
__device__ __forceinline__ unsigned long long f2pack(float x, float y) {
    unsigned long long r;
    asm("mov.b64 %0, {%1, %2};" : "=l"(r) : "f"(x), "f"(y));
    return r;
}
__device__ __forceinline__ void f2unpack(unsigned long long v, float& x, float& y) {
    asm("mov.b64 {%0, %1}, %2;" : "=f"(x), "=f"(y) : "l"(v));
}
__device__ __forceinline__ unsigned long long f2fma(unsigned long long a,
                                                    unsigned long long b,
                                                    unsigned long long c) {
    unsigned long long d;
    asm("fma.rn.f32x2 %0, %1, %2, %3;" : "=l"(d) : "l"(a), "l"(b), "l"(c));
    return d;
}

// ---------------- pack kernels ----------------
__global__ void pack_rec_kernel(GatePtrs p) {
    unsigned idx = blockIdx.x * blockDim.x + threadIdx.x;
    unsigned k = idx >> 12;
    unsigned j = idx & 4095;
    unsigned g = j >> 10;
    unsigned n = j & 1023;
    g_Wh[idx] = p.Wh[g][k * 1024u + n];
    if (idx < NJ) g_bias[idx] = p.bx[g][n] + p.bh[g][n];
}

__global__ void pack_xs_kernel(const float* __restrict__ x) {
    int m = blockIdx.x;
    int k = threadIdx.x * 4;
    float4 v = *(const float4*)(x + (size_t)m * DIM + k);
    __nv_bfloat16 h0 = __float2bfloat16(v.x);
    __nv_bfloat16 h1 = __float2bfloat16(v.y);
    __nv_bfloat16 h2 = __float2bfloat16(v.z);
    __nv_bfloat16 h3 = __float2bfloat16(v.w);
    __nv_bfloat16 l0 = __float2bfloat16(v.x - __bfloat162float(h0));
    __nv_bfloat16 l1 = __float2bfloat16(v.y - __bfloat162float(h1));
    __nv_bfloat16 l2 = __float2bfloat16(v.z - __bfloat162float(h2));
    __nv_bfloat16 l3 = __float2bfloat16(v.w - __bfloat162float(h3));
    size_t base = (size_t)m * 2048 + k;
    *(__nv_bfloat162*)(g_Xs + base)            = __halves2bfloat162(h0, h1);
    *(__nv_bfloat162*)(g_Xs + base + 2)        = __halves2bfloat162(h2, h3);
    *(__nv_bfloat162*)(g_Xs + base + 1024)     = __halves2bfloat162(l0, l1);
    *(__nv_bfloat162*)(g_Xs + base + 1024 + 2) = __halves2bfloat162(l2, l3);
}

__global__ void pack_ws_kernel(GatePtrs p) {
    __shared__ float s[32][33];
    int kt = blockIdx.x, nt = blockIdx.y, g = blockIdx.z;
    int tx = threadIdx.x & 31;
    int ty = threadIdx.x >> 5;
    const float* W = p.Wx[g];
#pragma unroll
    for (int i = 0; i < 4; i++) {
        int r = ty + i * 8;
        s[r][tx] = W[(size_t)(kt * 32 + r) * 1024 + nt * 32 + tx];
    }
    __syncthreads();
#pragma unroll
    for (int i = 0; i < 4; i++) {
        int r2 = ty + i * 8;
        float v = s[tx][r2];
        __nv_bfloat16 hi = __float2bfloat16(v);
        __nv_bfloat16 lo = __float2bfloat16(v - __bfloat162float(hi));
        size_t j = (size_t)g * 1024 + nt * 32 + r2;
        size_t kcol = kt * 32 + tx;
        g_Ws[j * 2048 + kcol]        = hi;
        g_Ws[j * 2048 + 1024 + kcol] = lo;
    }
}

// ---------------- xproj: HMMA (mma.sync bf16) GEMM ----------------
// G[32768 x 4096] = Xs @ Ws^T over K' = 3072 (segments (hi,hi),(hi,lo),(lo,hi))
#define BMT 256
#define BNT 128
#define BKT 32
#define NST 4
#define STAGE_BYTES ((BMT + BNT) * BKT * 2)   // 24576
#define XP_SMEM (NST * STAGE_BYTES)           // 98304
#define NKI 96                                // 3072 / 32

// smem addr with xor swizzle on 16B chunks (4 chunks per 64B row)
__device__ __forceinline__ uint32_t swz(uint32_t base, int row, int chunk) {
    return base + row * 64 + (((uint32_t)chunk ^ (((uint32_t)row >> 1) & 3)) << 4);
}

__global__ __launch_bounds__(512, 1) void xproj_mma_kernel() {
    extern __shared__ char smem[];
    const uint32_t sbase = smem_to_u32(smem);
    const int tid = threadIdx.x;
    const int wid = tid >> 5;
    const int lid = tid & 31;

    const int mtile = blockIdx.x >> 5;   // 0..127
    const int ntile = blockIdx.x & 31;   // 0..31
    const int m0 = mtile * BMT;
    const int n0 = ntile * BNT;

    const int wm = wid >> 2;   // 0..3  (64 rows each)
    const int wn = wid & 3;    // 0..3  (32 cols each)

    // ldmatrix lane-address precompute
    // A (x4): mi=lid>>3: row = wm*64 + mf*16 + (mi&1)*8 + (lid&7); chunkbit = mi>>1
    int aRow[4], aSw[4];
#pragma unroll
    for (int mf = 0; mf < 4; mf++) {
        int r = wm * 64 + mf * 16 + (((lid >> 3) & 1) << 3) + (lid & 7);
        aRow[mf] = r * 64;
        aSw[mf] = (r >> 1) & 3;
    }
    const int aBit = lid >> 4;            // chunk bit for A
    // B (x4): mi=lid>>3: row = wn*32 + np*16 + (mi>>1)*8 + (lid&7); chunkbit = mi&1
    int bRow[2], bSw[2];
#pragma unroll
    for (int np = 0; np < 2; np++) {
        int r = wn * 32 + np * 16 + (((lid >> 4) & 1) << 3) + (lid & 7);
        bRow[np] = r * 64;
        bSw[np] = (r >> 1) & 3;
    }
    const int bBit = (lid >> 3) & 1;

    float acc[4][4][4];
#pragma unroll
    for (int mf = 0; mf < 4; mf++)
#pragma unroll
        for (int nf = 0; nf < 4; nf++)
#pragma unroll
            for (int q = 0; q < 4; q++) acc[mf][nf][q] = 0.0f;

    // stage loader: A 1024 tasks + B 512 tasks, 3 x 16B per thread
    auto load_stage = [&](int kt, int st) {
        int seg = kt >> 5;
        int koff = (kt & 31) << 5;
        int a_col = koff + ((seg == 2) ? 1024 : 0);
        int b_col = koff + ((seg == 1) ? 1024 : 0);
        uint32_t sa = sbase + st * STAGE_BYTES;
        uint32_t sb = sa + BMT * BKT * 2;
#pragma unroll
        for (int i = 0; i < 3; i++) {
            int task = tid + i * 512;
            if (task < 1024) {
                int row = task >> 2, ch = task & 3;
                cp_async16(swz(sa, row, ch),
                           g_Xs + (size_t)(m0 + row) * 2048 + a_col + ch * 8);
            } else {
                int t2 = task - 1024;
                int row = t2 >> 2, ch = t2 & 3;
                cp_async16(swz(sb, row, ch),
                           g_Ws + (size_t)(n0 + row) * 2048 + b_col + ch * 8);
            }
        }
        cp_commit();
    };

    // prologue: stages 0..2
    load_stage(0, 0);
    load_stage(1, 1);
    load_stage(2, 2);

    for (int kt = 0; kt < NKI; kt++) {
        CP_WAIT2();
        __syncthreads();
        if (kt + 3 < NKI) load_stage(kt + 3, (kt + 3) & 3);
        else cp_commit();   // keep group accounting uniform

        uint32_t sa = sbase + (kt & 3) * STAGE_BYTES;
        uint32_t sb = sa + BMT * BKT * 2;

#pragma unroll
        for (int k16 = 0; k16 < 2; k16++) {
            uint32_t bf[4][2];
#pragma unroll
            for (int np = 0; np < 2; np++) {
                uint32_t addr = sb + bRow[np]
                              + (((uint32_t)(k16 * 2 + bBit) ^ bSw[np]) << 4);
                uint32_t r0, r1, r2, r3;
                LDSM_X4(r0, r1, r2, r3, addr);
                bf[np * 2][0] = r0; bf[np * 2][1] = r1;
                bf[np * 2 + 1][0] = r2; bf[np * 2 + 1][1] = r3;
            }
#pragma unroll
            for (int mf = 0; mf < 4; mf++) {
                uint32_t af[4];
                uint32_t addr = sa + aRow[mf]
                              + (((uint32_t)(k16 * 2 + aBit) ^ aSw[mf]) << 4);
                LDSM_X4(af[0], af[1], af[2], af[3], addr);
#pragma unroll
                for (int nf = 0; nf < 4; nf++)
                    mma_bf16(acc[mf][nf], af, bf[nf]);
            }
        }
    }

    // epilogue: bias add + fp32 store
    const int row_base = m0 + wm * 64 + (lid >> 2);
    const int col_base = n0 + wn * 32 + (lid & 3) * 2;
#pragma unroll
    for (int nf = 0; nf < 4; nf++) {
        int col = col_base + nf * 8;
        float2 bb = *(const float2*)&g_bias[col];
#pragma unroll
        for (int mf = 0; mf < 4; mf++) {
            int r = row_base + mf * 16;
            float2 v0 = make_float2(acc[mf][nf][0] + bb.x, acc[mf][nf][1] + bb.y);
            float2 v1 = make_float2(acc[mf][nf][2] + bb.x, acc[mf][nf][3] + bb.y);
            *(float2*)&g_G[(size_t)r * NJ + col]       = v0;
            *(float2*)&g_G[(size_t)(r + 8) * NJ + col] = v1;
        }
    }
}

// ---------------- persistent recurrence (fp32 f32x2, double-buffered staging) ----------------
#define RB  128
#define CPB 8
#define RKT 64

__device__ __forceinline__ float sigm(float v) {
    return 1.0f / (1.0f + expf(-v));
}

__global__ __launch_bounds__(256) void lstm_steps_kernel(float* __restrict__ out) {
    __shared__ float h_s[RKT][66];
    __shared__ float w_s[RKT][32];
    __shared__ float pre_s[BATCH][33];

    const int tid = threadIdx.x;
    const int n0 = blockIdx.x * CPB;

    const int col = tid & 31;
    const int jcol = (col >> 3) * HID + n0 + (col & 7);
    const int brow = (tid >> 5) * 8;

    const int oc = tid & 7;
    const int b0 = (tid >> 3) * 2;

    float c0 = 0.0f, c1 = 0.0f;

    float* out_hseq = out;
    float* out_h = out + (size_t)SEQ * BATCH * HID;
    float* out_c = out_h + BATCH * HID;

    int wj[8];
#pragma unroll
    for (int l = 0; l < 8; l++) {
        int idx = tid + l * 256;
        int c = idx & 31;
        wj[l] = (c >> 3) * HID + n0 + (c & 7);
    }

    for (int t = 0; t < SEQ; t++) {
        unsigned long long acc[4] = {0ull, 0ull, 0ull, 0ull};

        float gpre[8];
        {
            const float* Gt = g_G + (size_t)t * BATCH * NJ;
#pragma unroll
            for (int p = 0; p < 4; p++) {
                int b = brow + 2 * p;
                gpre[2 * p]     = __ldg(Gt + (size_t)b * NJ + jcol);
                gpre[2 * p + 1] = __ldg(Gt + (size_t)(b + 1) * NJ + jcol);
            }
        }

        if (t > 0) {
            const float* hprev = out_hseq + (size_t)(t - 1) * BATCH * HID;
            float hr[16], wr[8];
#pragma unroll
            for (int l = 0; l < 16; l++) {
                int idx = tid + l * 256;
                hr[l] = __ldcg(hprev + (idx >> 6) * HID + (idx & 63));
            }
#pragma unroll
            for (int l = 0; l < 8; l++) {
                int idx = tid + l * 256;
                wr[l] = g_Wh[(size_t)(idx >> 5) * NJ + wj[l]];
            }

            for (int kt = 0; kt < HID; kt += RKT) {
#pragma unroll
                for (int l = 0; l < 16; l++) {
                    int idx = tid + l * 256;
                    h_s[idx & 63][idx >> 6] = hr[l];
                }
#pragma unroll
                for (int l = 0; l < 8; l++) {
                    int idx = tid + l * 256;
                    w_s[idx >> 5][idx & 31] = wr[l];
                }
                __syncthreads();

                if (kt + RKT < HID) {
                    int kn = kt + RKT;
#pragma unroll
                    for (int l = 0; l < 16; l++) {
                        int idx = tid + l * 256;
                        hr[l] = __ldcg(hprev + (idx >> 6) * HID + kn + (idx & 63));
                    }
#pragma unroll
                    for (int l = 0; l < 8; l++) {
                        int idx = tid + l * 256;
                        wr[l] = g_Wh[(size_t)(kn + (idx >> 5)) * NJ + wj[l]];
                    }
                }

#pragma unroll
                for (int kk = 0; kk < RKT; kk++) {
                    float w = w_s[kk][col];
                    unsigned long long wp = f2pack(w, w);
#pragma unroll
                    for (int p = 0; p < 4; p++) {
                        unsigned long long hp =
                            *(const unsigned long long*)&h_s[kk][brow + 2 * p];
                        acc[p] = f2fma(hp, wp, acc[p]);
                    }
                }
                __syncthreads();
            }
        }

        {
#pragma unroll
            for (int p = 0; p < 4; p++) {
                float lo, hi;
                f2unpack(acc[p], lo, hi);
                int b = brow + 2 * p;
                pre_s[b][col]     = lo + gpre[2 * p];
                pre_s[b + 1][col] = hi + gpre[2 * p + 1];
            }
        }
        __syncthreads();

        {
            float fA = sigm(pre_s[b0][oc]);
            float iA = sigm(pre_s[b0][8 + oc]);
            float oA = sigm(pre_s[b0][16 + oc]);
            float gA = tanhf(pre_s[b0][24 + oc]);
            c0 = fA * c0 + iA * gA;
            float hA = oA * tanhf(c0);

            float fB = sigm(pre_s[b0 + 1][oc]);
            float iB = sigm(pre_s[b0 + 1][8 + oc]);
            float oB = sigm(pre_s[b0 + 1][16 + oc]);
            float gB = tanhf(pre_s[b0 + 1][24 + oc]);
            c1 = fB * c1 + iB * gB;
            float hB = oB * tanhf(c1);

            size_t idxA = (size_t)t * BATCH * HID + (size_t)b0 * HID + n0 + oc;
            size_t idxB = idxA + HID;
            out_hseq[idxA] = hA;
            out_hseq[idxB] = hB;
            if (t == SEQ - 1) {
                out_h[(size_t)b0 * HID + n0 + oc] = hA;
                out_h[(size_t)(b0 + 1) * HID + n0 + oc] = hB;
                out_c[(size_t)b0 * HID + n0 + oc] = c0;
                out_c[(size_t)(b0 + 1) * HID + n0 + oc] = c1;
            }
        }

        if (t < SEQ - 1) {
            __threadfence();
            __syncthreads();
            if (tid == 0) {
                unsigned gen = atomicAdd(&g_bar_gen, 0u);
                unsigned arrived = atomicAdd(&g_bar_count, 1u);
                if (arrived == RB - 1) {
                    g_bar_count = 0u;
                    __threadfence();
                    atomicAdd(&g_bar_gen, 1u);
                } else {
                    while (atomicAdd(&g_bar_gen, 0u) == gen) { __nanosleep(64); }
                }
            }
            __syncthreads();
        }
    }
}

// ---------------- launch ----------------
extern "C" void kernel_launch(void* const* d_in, const int* in_sizes, int n_in,
                              void* d_out, int out_size) {
    const float* x = nullptr;
    const float* W[8] = {};
    const float* Bv[8] = {};
    int wi = 0, bi = 0;
    for (int i = 0; i < n_in; i++) {
        long long sz = in_sizes[i];
        if (sz == (long long)SEQ * BATCH * DIM) {
            x = (const float*)d_in[i];
        } else if (sz == (long long)DIM * HID) {
            if (wi < 8) W[wi++] = (const float*)d_in[i];
        } else if (sz == HID) {
            if (bi < 8) Bv[bi++] = (const float*)d_in[i];
        }
    }
    if (!x || wi != 8 || bi != 8) return;

    GatePtrs p;
    for (int g = 0; g < 4; g++) {
        p.Wx[g] = W[g];
        p.Wh[g] = W[4 + g];
        p.bx[g] = Bv[g];
        p.bh[g] = Bv[4 + g];
    }

    float* outf = (float*)d_out;

    cudaFuncSetAttribute(xproj_mma_kernel,
                         cudaFuncAttributeMaxDynamicSharedMemorySize, XP_SMEM);

    pack_rec_kernel<<<(DIM * NJ) / 1024, 1024>>>(p);
    pack_xs_kernel<<<MROWS, 256>>>(x);
    dim3 wgrid(32, 32, 4);
    pack_ws_kernel<<<wgrid, 256>>>(p);

    xproj_mma_kernel<<<128 * 32, 512, XP_SMEM>>>();

    lstm_steps_kernel<<<RB, 256>>>(outf);
}

// round 4
// speedup vs baseline: 2.9970x; 2.9970x over previous
#include <cuda_runtime.h>
#include <cuda_bf16.h>
#include <cstdint>

#define SEQ   512
#define BATCH 64
#define DIM   1024
#define HID   1024
#define NJ    4096            // 4 gates * HID
#define MROWS (SEQ*BATCH)     // 32768

// ---------------- scratch (static device allocs only) ----------------
__device__ float g_G[(size_t)SEQ * BATCH * NJ];          // [m][j] fp32
__device__ __nv_bfloat16 g_Xs[(size_t)MROWS * 2048];     // [m][hi(1024)|lo(1024)]
__device__ __nv_bfloat16 g_Ws[(size_t)NJ * 2048];        // [j][hi|lo]  (Wx^T)
__device__ __nv_bfloat16 g_Whs[(size_t)NJ * 2048];       // [cb][hi|lo] (Wh^T, block-packed)
__device__ __nv_bfloat16 g_Hs[2][(size_t)BATCH * 2048];  // h staging [buf][b][hi|lo]
__device__ float g_bias[NJ];                             // bx+bh (gate-major j)
__device__ unsigned int g_bar_count;
__device__ unsigned int g_bar_gen;

struct GatePtrs {
    const float* Wx[4];
    const float* Wh[4];
    const float* bx[4];
    const float* bh[4];
};

// ---------------- small helpers ----------------
__device__ __forceinline__ uint32_t smem_to_u32(const void* p) {
    uint32_t a;
    asm("{ .reg .u64 t; cvta.to.shared.u64 t, %1; cvt.u32.u64 %0, t; }"
        : "=r"(a) : "l"(p));
    return a;
}
__device__ __forceinline__ void cp_async16(uint32_t saddr, const void* g) {
    asm volatile("cp.async.cg.shared.global [%0], [%1], 16;"
                 :: "r"(saddr), "l"(g) : "memory");
}
__device__ __forceinline__ void cp_commit() {
    asm volatile("cp.async.commit_group;" ::: "memory");
}
#define CP_WAIT2() asm volatile("cp.async.wait_group 2;" ::: "memory")
#define CP_WAIT0() asm volatile("cp.async.wait_group 0;" ::: "memory")

#define LDSM_X4(r0, r1, r2, r3, addr) \
    asm volatile("ldmatrix.sync.aligned.m8n8.x4.shared.b16 {%0,%1,%2,%3}, [%4];" \
        : "=r"(r0), "=r"(r1), "=r"(r2), "=r"(r3) : "r"(addr))

__device__ __forceinline__ void mma_bf16(float* c, const uint32_t* a, const uint32_t* b) {
    asm volatile(
        "mma.sync.aligned.m16n8k16.row.col.f32.bf16.bf16.f32 "
        "{%0,%1,%2,%3}, {%4,%5,%6,%7}, {%8,%9}, {%0,%1,%2,%3};"
        : "+f"(c[0]), "+f"(c[1]), "+f"(c[2]), "+f"(c[3])
        : "r"(a[0]), "r"(a[1]), "r"(a[2]), "r"(a[3]), "r"(b[0]), "r"(b[1]));
}

// smem addr with xor swizzle on 16B chunks (4 chunks per 64B row)
__device__ __forceinline__ uint32_t swz(uint32_t base, int row, int chunk) {
    return base + row * 64 + (((uint32_t)chunk ^ (((uint32_t)row >> 1) & 3)) << 4);
}

__device__ __forceinline__ float sigm(float v) {
    return 1.0f / (1.0f + expf(-v));
}

// ---------------- pack kernels ----------------
__global__ void pack_bias_kernel(GatePtrs p) {
    int idx = blockIdx.x * blockDim.x + threadIdx.x;   // 0..4095, j = g*1024+n
    int g = idx >> 10, n = idx & 1023;
    g_bias[idx] = p.bx[g][n] + p.bh[g][n];
}

__global__ void pack_xs_kernel(const float* __restrict__ x) {
    int m = blockIdx.x;
    int k = threadIdx.x * 4;
    float4 v = *(const float4*)(x + (size_t)m * DIM + k);
    __nv_bfloat16 h0 = __float2bfloat16(v.x);
    __nv_bfloat16 h1 = __float2bfloat16(v.y);
    __nv_bfloat16 h2 = __float2bfloat16(v.z);
    __nv_bfloat16 h3 = __float2bfloat16(v.w);
    __nv_bfloat16 l0 = __float2bfloat16(v.x - __bfloat162float(h0));
    __nv_bfloat16 l1 = __float2bfloat16(v.y - __bfloat162float(h1));
    __nv_bfloat16 l2 = __float2bfloat16(v.z - __bfloat162float(h2));
    __nv_bfloat16 l3 = __float2bfloat16(v.w - __bfloat162float(h3));
    size_t base = (size_t)m * 2048 + k;
    *(__nv_bfloat162*)(g_Xs + base)            = __halves2bfloat162(h0, h1);
    *(__nv_bfloat162*)(g_Xs + base + 2)        = __halves2bfloat162(h2, h3);
    *(__nv_bfloat162*)(g_Xs + base + 1024)     = __halves2bfloat162(l0, l1);
    *(__nv_bfloat162*)(g_Xs + base + 1024 + 2) = __halves2bfloat162(l2, l3);
}

__global__ void pack_ws_kernel(GatePtrs p) {
    __shared__ float s[32][33];
    int kt = blockIdx.x, nt = blockIdx.y, g = blockIdx.z;
    int tx = threadIdx.x & 31;
    int ty = threadIdx.x >> 5;
#pragma unroll
    for (int i = 0; i < 4; i++) {
        int r = ty + i * 8;
        s[r][tx] = p.Wx[g][(size_t)(kt * 32 + r) * 1024 + nt * 32 + tx];
    }
    __syncthreads();
#pragma unroll
    for (int i = 0; i < 4; i++) {
        int r2 = ty + i * 8;
        float v = s[tx][r2];
        __nv_bfloat16 hi = __float2bfloat16(v);
        __nv_bfloat16 lo = __float2bfloat16(v - __bfloat162float(hi));
        size_t j = (size_t)g * 1024 + nt * 32 + r2;
        size_t kcol = kt * 32 + tx;
        g_Ws[j * 2048 + kcol]        = hi;
        g_Ws[j * 2048 + 1024 + kcol] = lo;
    }
}

// Wh -> bf16 hi/lo split in block-packed layout:
// cb = blk*32 + (g*8+cc)  -> row of g_Whs; source col j = blk*8+cc of Wh[g]
__global__ void pack_whs_kernel(GatePtrs p) {
    int cb = blockIdx.x;            // 0..4095
    int blk = cb >> 5;
    int c = cb & 31;
    int g = c >> 3;
    int col = blk * 8 + (c & 7);
    const float* W = p.Wh[g];
    int k0 = threadIdx.x * 4;
#pragma unroll
    for (int q = 0; q < 4; q++) {
        int k = k0 + q;
        float v = W[(size_t)k * 1024 + col];
        __nv_bfloat16 hi = __float2bfloat16(v);
        __nv_bfloat16 lo = __float2bfloat16(v - __bfloat162float(hi));
        g_Whs[(size_t)cb * 2048 + k]        = hi;
        g_Whs[(size_t)cb * 2048 + 1024 + k] = lo;
    }
}

// ---------------- xproj: HMMA (mma.sync bf16) GEMM ----------------
#define BMT 256
#define BNT 128
#define BKT 32
#define NST 4
#define STAGE_BYTES ((BMT + BNT) * BKT * 2)   // 24576
#define XP_SMEM (NST * STAGE_BYTES)           // 98304
#define NKI 96                                // 3072 / 32

__global__ __launch_bounds__(512, 1) void xproj_mma_kernel() {
    extern __shared__ char smem[];
    const uint32_t sbase = smem_to_u32(smem);
    const int tid = threadIdx.x;
    const int wid = tid >> 5;
    const int lid = tid & 31;

    const int mtile = blockIdx.x >> 5;
    const int ntile = blockIdx.x & 31;
    const int m0 = mtile * BMT;
    const int n0 = ntile * BNT;

    const int wm = wid >> 2;
    const int wn = wid & 3;

    int aRow[4], aSw[4];
#pragma unroll
    for (int mf = 0; mf < 4; mf++) {
        int r = wm * 64 + mf * 16 + (((lid >> 3) & 1) << 3) + (lid & 7);
        aRow[mf] = r * 64;
        aSw[mf] = (r >> 1) & 3;
    }
    const int aBit = lid >> 4;
    int bRow[2], bSw[2];
#pragma unroll
    for (int np = 0; np < 2; np++) {
        int r = wn * 32 + np * 16 + (((lid >> 4) & 1) << 3) + (lid & 7);
        bRow[np] = r * 64;
        bSw[np] = (r >> 1) & 3;
    }
    const int bBit = (lid >> 3) & 1;

    float acc[4][4][4];
#pragma unroll
    for (int mf = 0; mf < 4; mf++)
#pragma unroll
        for (int nf = 0; nf < 4; nf++)
#pragma unroll
            for (int q = 0; q < 4; q++) acc[mf][nf][q] = 0.0f;

    auto load_stage = [&](int kt, int st) {
        int seg = kt >> 5;
        int koff = (kt & 31) << 5;
        int a_col = koff + ((seg == 2) ? 1024 : 0);
        int b_col = koff + ((seg == 1) ? 1024 : 0);
        uint32_t sa = sbase + st * STAGE_BYTES;
        uint32_t sb = sa + BMT * BKT * 2;
#pragma unroll
        for (int i = 0; i < 3; i++) {
            int task = tid + i * 512;
            if (task < 1024) {
                int row = task >> 2, ch = task & 3;
                cp_async16(swz(sa, row, ch),
                           g_Xs + (size_t)(m0 + row) * 2048 + a_col + ch * 8);
            } else {
                int t2 = task - 1024;
                int row = t2 >> 2, ch = t2 & 3;
                cp_async16(swz(sb, row, ch),
                           g_Ws + (size_t)(n0 + row) * 2048 + b_col + ch * 8);
            }
        }
        cp_commit();
    };

    load_stage(0, 0);
    load_stage(1, 1);
    load_stage(2, 2);

    for (int kt = 0; kt < NKI; kt++) {
        CP_WAIT2();
        __syncthreads();
        if (kt + 3 < NKI) load_stage(kt + 3, (kt + 3) & 3);
        else cp_commit();

        uint32_t sa = sbase + (kt & 3) * STAGE_BYTES;
        uint32_t sb = sa + BMT * BKT * 2;

#pragma unroll
        for (int k16 = 0; k16 < 2; k16++) {
            uint32_t bf[4][2];
#pragma unroll
            for (int np = 0; np < 2; np++) {
                uint32_t addr = sb + bRow[np]
                              + (((uint32_t)(k16 * 2 + bBit) ^ bSw[np]) << 4);
                uint32_t r0, r1, r2, r3;
                LDSM_X4(r0, r1, r2, r3, addr);
                bf[np * 2][0] = r0; bf[np * 2][1] = r1;
                bf[np * 2 + 1][0] = r2; bf[np * 2 + 1][1] = r3;
            }
#pragma unroll
            for (int mf = 0; mf < 4; mf++) {
                uint32_t af[4];
                uint32_t addr = sa + aRow[mf]
                              + (((uint32_t)(k16 * 2 + aBit) ^ aSw[mf]) << 4);
                LDSM_X4(af[0], af[1], af[2], af[3], addr);
#pragma unroll
                for (int nf = 0; nf < 4; nf++)
                    mma_bf16(acc[mf][nf], af, bf[nf]);
            }
        }
    }

    const int row_base = m0 + wm * 64 + (lid >> 2);
    const int col_base = n0 + wn * 32 + (lid & 3) * 2;
#pragma unroll
    for (int nf = 0; nf < 4; nf++) {
        int col = col_base + nf * 8;
        float2 bb = *(const float2*)&g_bias[col];
#pragma unroll
        for (int mf = 0; mf < 4; mf++) {
            int r = row_base + mf * 16;
            float2 v0 = make_float2(acc[mf][nf][0] + bb.x, acc[mf][nf][1] + bb.y);
            float2 v1 = make_float2(acc[mf][nf][2] + bb.x, acc[mf][nf][3] + bb.y);
            *(float2*)&g_G[(size_t)r * NJ + col]       = v0;
            *(float2*)&g_G[(size_t)(r + 8) * NJ + col] = v1;
        }
    }
}

// ---------------- persistent recurrence: HMMA bf16-split ----------------
// Per step, per block (128 blocks, 8 hidden cols each):
//   pre[64 x 32] = h(t-1)[64 x 1024] @ WhT_block[32 x 1024]  (3-term bf16 split)
// B (Wh split, 64 chunks of 32x32) lives in SMEM for the whole kernel.
#define RB 128
// smem layout (dynamic):
#define RSM_B     0            // 64 chunks * 2048B = 131072
#define RSM_A     131072       // 4 stages * 8192B  = 32768
#define RSM_PRE   163840       // 64*33 floats      = 8448
#define RSM_TOTAL 172288

__global__ __launch_bounds__(256, 1) void lstm_mma_kernel(float* __restrict__ out) {
    extern __shared__ char smem[];
    const uint32_t sbase = smem_to_u32(smem);
    const uint32_t Bbase = sbase + RSM_B;
    const uint32_t Abase = sbase + RSM_A;
    float* pre_s = (float*)(smem + RSM_PRE);   // [64][33]

    const int tid = threadIdx.x;
    const int wid = tid >> 5;
    const int lid = tid & 31;
    const int blk = blockIdx.x;

    // warp tiling: wm 0..3 (m16 each over batch 64), wn 0..1 (n16 each over 32 cols)
    const int wm = wid & 3;
    const int wn = wid >> 2;

    // ldmatrix lane addresses
    const int arow = wm * 16 + (((lid >> 3) & 1) << 3) + (lid & 7);
    const int aR = arow * 64, aS = (arow >> 1) & 3;
    const int aBit = lid >> 4;
    const int brow = wn * 16 + (((lid >> 4) & 1) << 3) + (lid & 7);
    const int bR = brow * 64, bS = (brow >> 1) & 3;
    const int bBit = (lid >> 3) & 1;

    // gate-thread mapping
    const int oc = tid & 7;           // local hidden col 0..7
    const int b0 = (tid >> 3) * 2;    // batch pair
    const int ncol = blk * 8 + oc;    // global hidden col

    float* out_hseq = out;
    float* out_h = out + (size_t)SEQ * BATCH * HID;
    float* out_c = out_h + BATCH * HID;

    // ---- preload B (Wh split) into smem: 64 chunks of 32 rows x 32 k ----
#pragma unroll 4
    for (int i = 0; i < 32; i++) {
        int task = tid + i * 256;           // 0..8191
        int chunk = task >> 7;
        int rem = task & 127;
        int r = rem >> 2;
        int ci = rem & 3;
        int col = (chunk < 32) ? chunk * 32 : 1024 + (chunk - 32) * 32;
        cp_async16(swz(Bbase + chunk * 2048, r, ci),
                   g_Whs + (size_t)(blk * 32 + r) * 2048 + col + ci * 8);
    }
    cp_commit();
    CP_WAIT0();
    __syncthreads();

    float c0 = 0.0f, c1 = 0.0f;

    for (int t = 0; t < SEQ; t++) {
        // prefetch G[t] for gate threads (DRAM; overlaps GEMM)
        float gpre[8];
        {
            const float* Gt = g_G + (size_t)t * BATCH * NJ;
#pragma unroll
            for (int g = 0; g < 4; g++) {
                gpre[2 * g]     = __ldg(Gt + (size_t)b0 * NJ + g * 1024 + ncol);
                gpre[2 * g + 1] = __ldg(Gt + (size_t)(b0 + 1) * NJ + g * 1024 + ncol);
            }
        }

        float acc[2][4];
#pragma unroll
        for (int nf = 0; nf < 2; nf++)
#pragma unroll
            for (int q = 0; q < 4; q++) acc[nf][q] = 0.0f;

        if (t > 0) {
            const __nv_bfloat16* hprev = g_Hs[(t - 1) & 1];

            // A stage loader: stage s covers 64 k-elems (two 32k sub-tiles)
            auto load_astage = [&](int s) {
                int a_col = (s < 16) ? s * 64 : 1024 + (s - 16) * 64;
                uint32_t st = Abase + (s & 3) * 8192;
#pragma unroll
                for (int i = 0; i < 2; i++) {
                    int task = tid + i * 256;     // 0..511
                    int r = task >> 3;
                    int ch = task & 7;
                    int sub = ch >> 2;
                    int ci = ch & 3;
                    cp_async16(swz(st + sub * 4096, r, ci),
                               hprev + (size_t)r * 2048 + a_col + ch * 8);
                }
                cp_commit();
            };

            load_astage(0);
            load_astage(1);
            load_astage(2);

            for (int s = 0; s < 32; s++) {
                CP_WAIT2();
                __syncthreads();
                if (s + 3 < 32) load_astage(s + 3);
                else cp_commit();

                uint32_t sa = Abase + (s & 3) * 8192;
                const bool phase1 = (s < 16);
                const int kk2 = phase1 ? s * 2 : (s - 16) * 2;

#pragma unroll
                for (int sub = 0; sub < 2; sub++) {
                    uint32_t tileA = sa + sub * 4096;
                    int bhi = kk2 + sub;                 // W_hi chunk
                    uint32_t cbHi = Bbase + bhi * 2048;
                    uint32_t cbLo = Bbase + (32 + bhi) * 2048;
#pragma unroll
                    for (int k16 = 0; k16 < 2; k16++) {
                        uint32_t af[4];
                        LDSM_X4(af[0], af[1], af[2], af[3],
                                tileA + aR + (((uint32_t)(k16 * 2 + aBit) ^ aS) << 4));
                        uint32_t b0r, b1r, b2r, b3r;
                        LDSM_X4(b0r, b1r, b2r, b3r,
                                cbHi + bR + (((uint32_t)(k16 * 2 + bBit) ^ bS) << 4));
                        uint32_t bf0[2] = {b0r, b1r}, bf1[2] = {b2r, b3r};
                        mma_bf16(acc[0], af, bf0);
                        mma_bf16(acc[1], af, bf1);
                        if (phase1) {
                            LDSM_X4(b0r, b1r, b2r, b3r,
                                    cbLo + bR + (((uint32_t)(k16 * 2 + bBit) ^ bS) << 4));
                            uint32_t bl0[2] = {b0r, b1r}, bl1[2] = {b2r, b3r};
                            mma_bf16(acc[0], af, bl0);
                            mma_bf16(acc[1], af, bl1);
                        }
                    }
                }
            }
        }

        // write fragments to pre_s
        {
            int r = wm * 16 + (lid >> 2);
            int cb2 = wn * 16 + (lid & 3) * 2;
#pragma unroll
            for (int nf = 0; nf < 2; nf++) {
                int c = cb2 + nf * 8;
                pre_s[r * 33 + c]           = acc[nf][0];
                pre_s[r * 33 + c + 1]       = acc[nf][1];
                pre_s[(r + 8) * 33 + c]     = acc[nf][2];
                pre_s[(r + 8) * 33 + c + 1] = acc[nf][3];
            }
        }
        __syncthreads();

        // gate math: cols in pre_s are [f0..7 | i0..7 | o0..7 | g0..7]
        {
            float fA = sigm(pre_s[b0 * 33 + oc]           + gpre[0]);
            float iA = sigm(pre_s[b0 * 33 + 8 + oc]       + gpre[2]);
            float oA = sigm(pre_s[b0 * 33 + 16 + oc]      + gpre[4]);
            float gA = tanhf(pre_s[b0 * 33 + 24 + oc]     + gpre[6]);
            c0 = fA * c0 + iA * gA;
            float hA = oA * tanhf(c0);

            float fB = sigm(pre_s[(b0 + 1) * 33 + oc]       + gpre[1]);
            float iB = sigm(pre_s[(b0 + 1) * 33 + 8 + oc]   + gpre[3]);
            float oB = sigm(pre_s[(b0 + 1) * 33 + 16 + oc]  + gpre[5]);
            float gB = tanhf(pre_s[(b0 + 1) * 33 + 24 + oc] + gpre[7]);
            c1 = fB * c1 + iB * gB;
            float hB = oB * tanhf(c1);

            // fp32 outputs
            size_t idxA = (size_t)t * BATCH * HID + (size_t)b0 * HID + ncol;
            out_hseq[idxA]       = hA;
            out_hseq[idxA + HID] = hB;

            // bf16 hi/lo staging for next step
            __nv_bfloat16* Hc = g_Hs[t & 1];
            __nv_bfloat16 hiA = __float2bfloat16(hA);
            __nv_bfloat16 hiB = __float2bfloat16(hB);
            Hc[(size_t)b0 * 2048 + ncol]              = hiA;
            Hc[(size_t)b0 * 2048 + 1024 + ncol]       = __float2bfloat16(hA - __bfloat162float(hiA));
            Hc[(size_t)(b0 + 1) * 2048 + ncol]        = hiB;
            Hc[(size_t)(b0 + 1) * 2048 + 1024 + ncol] = __float2bfloat16(hB - __bfloat162float(hiB));

            if (t == SEQ - 1) {
                out_h[(size_t)b0 * HID + ncol] = hA;
                out_h[(size_t)(b0 + 1) * HID + ncol] = hB;
                out_c[(size_t)b0 * HID + ncol] = c0;
                out_c[(size_t)(b0 + 1) * HID + ncol] = c1;
            }
        }

        // grid barrier
        if (t < SEQ - 1) {
            __threadfence();
            __syncthreads();
            if (tid == 0) {
                unsigned gen = *(volatile unsigned int*)&g_bar_gen;
                unsigned arrived = atomicAdd(&g_bar_count, 1u);
                if (arrived == RB - 1) {
                    g_bar_count = 0u;
                    __threadfence();
                    atomicAdd(&g_bar_gen, 1u);
                } else {
                    while (*(volatile unsigned int*)&g_bar_gen == gen) {
                        __nanosleep(32);
                    }
                }
            }
            __syncthreads();
        }
    }
}

// ---------------- launch ----------------
extern "C" void kernel_launch(void* const* d_in, const int* in_sizes, int n_in,
                              void* d_out, int out_size) {
    const float* x = nullptr;
    const float* W[8] = {};
    const float* Bv[8] = {};
    int wi = 0, bi = 0;
    for (int i = 0; i < n_in; i++) {
        long long sz = in_sizes[i];
        if (sz == (long long)SEQ * BATCH * DIM) {
            x = (const float*)d_in[i];
        } else if (sz == (long long)DIM * HID) {
            if (wi < 8) W[wi++] = (const float*)d_in[i];
        } else if (sz == HID) {
            if (bi < 8) Bv[bi++] = (const float*)d_in[i];
        }
    }
    if (!x || wi != 8 || bi != 8) return;

    GatePtrs p;
    for (int g = 0; g < 4; g++) {
        p.Wx[g] = W[g];
        p.Wh[g] = W[4 + g];
        p.bx[g] = Bv[g];
        p.bh[g] = Bv[4 + g];
    }

    float* outf = (float*)d_out;

    cudaFuncSetAttribute(xproj_mma_kernel,
                         cudaFuncAttributeMaxDynamicSharedMemorySize, XP_SMEM);
    cudaFuncSetAttribute(lstm_mma_kernel,
                         cudaFuncAttributeMaxDynamicSharedMemorySize, RSM_TOTAL);

    pack_bias_kernel<<<4, 1024>>>(p);
    pack_xs_kernel<<<MROWS, 256>>>(x);
    dim3 wgrid(32, 32, 4);
    pack_ws_kernel<<<wgrid, 256>>>(p);
    pack_whs_kernel<<<NJ, 256>>>(p);

    xproj_mma_kernel<<<128 * 32, 512, XP_SMEM>>>();

    lstm_mma_kernel<<<RB, 256, RSM_TOTAL>>>(outf);
}